// round 4
// baseline (speedup 1.0000x reference)
#include <cuda_runtime.h>

// EMA over x[32, 4096, 256] fp32, adjust=True, period=25.
// Round-4: float4 lanes (LDG.128/STG.128), 16 chunks of 256 (T split), each
// chunk warm-started 192 steps early from e=0 (oma^192 ~ 2e-7 << 1e-3).
// For t >= 207, w_t == 1.0f exactly in fp32 -> constant coefficients; only
// chunk 0 runs the true adjusted recurrence (reciprocals off-chain).
// Streaming stores (__stcs) keep input resident in L2 for warmup reuse.

#define B_DIM   32
#define T_DIM   4096
#define F_DIM   256
#define CHUNK   256
#define NCHUNK  16
#define WARMUP  192
#define UB      8            // timesteps per load batch

#define ALPHA_C (2.0f / 26.0f)
#define OMA_C   (1.0f - ALPHA_C)

#define ROWF4   (F_DIM / 4)  // float4s per T-row

__device__ __forceinline__ void load_batch(float4 (&d)[UB],
                                           const float4* __restrict__ p) {
#pragma unroll
    for (int i = 0; i < UB; i++)
        d[i] = __ldg(p + (size_t)i * ROWF4);
}

__device__ __forceinline__ float4 step4(float4 e, float4 x, float ca, float co) {
    e.x = fmaf(co, e.x, ca * x.x);
    e.y = fmaf(co, e.y, ca * x.y);
    e.z = fmaf(co, e.z, ca * x.z);
    e.w = fmaf(co, e.w, ca * x.w);
    return e;
}

// Constant-coefficient batch (w_t == 1): optionally store.
__device__ __forceinline__ void proc_const(const float4 (&xv)[UB], float4& e,
                                           float4* __restrict__ po, bool st) {
#pragma unroll
    for (int i = 0; i < UB; i++) {
        e = step4(e, xv[i], ALPHA_C, OMA_C);
        if (st) __stcs(po + (size_t)i * ROWF4, e);
    }
}

// Chunk-0 exact adjusted recurrence; p0 = oma^{t0} on entry.
__device__ __forceinline__ void proc_adj(const float4 (&xv)[UB], float4& e,
                                         float& p0, float4* __restrict__ po) {
    float rw[UB];
    float q = 1.0f;
#pragma unroll
    for (int i = 0; i < UB; i++) {
        q *= OMA_C;                     // compile-time powers
        float wt = 1.0f - p0 * q;       // >= alpha, never degenerate
        rw[i] = __fdividef(1.0f, wt);
    }
    p0 *= q;
#pragma unroll
    for (int i = 0; i < UB; i++) {
        e = step4(e, xv[i], ALPHA_C * rw[i], OMA_C * rw[i]);
        __stcs(po + (size_t)i * ROWF4, e);
    }
}

__global__ void __launch_bounds__(128)
ema_f4_kernel(const float* __restrict__ xs, float* __restrict__ outs) {
    int g     = blockIdx.x * blockDim.x + threadIdx.x;
    int lane  = g & 31;
    int w     = g >> 5;                  // warp id 0..1023
    int f_hi  = w & 1;                   // 2 groups of 128 features
    int chunk = (w >> 1) & (NCHUNK - 1); // 0..15
    int b     = w >> 5;                  // 0..31
    int f4idx = f_hi * 32 + lane;        // float4 index within row: 0..63

    size_t seq_base = ((size_t)b * T_DIM) * ROWF4 + f4idx;   // in float4 units
    const size_t STRIDE = (size_t)UB * ROWF4;
    const float4* __restrict__ x = (const float4*)xs;
    float4* __restrict__ po =
        (float4*)outs + seq_base + (size_t)chunk * CHUNK * ROWF4;

    float4 e = make_float4(0.f, 0.f, 0.f, 0.f);
    float4 buf0[UB], buf1[UB];

    if (chunk == 0) {
        const float4* __restrict__ px = x + seq_base;
        float p0 = 1.0f;
        load_batch(buf0, px); px += STRIDE;
#pragma unroll 1
        for (int t0 = 0; t0 < CHUNK; t0 += 2 * UB) {
            load_batch(buf1, px); px += STRIDE;
            proc_adj(buf0, e, p0, po); po += STRIDE;
            if (t0 + 2 * UB < CHUNK) { load_batch(buf0, px); px += STRIDE; }
            proc_adj(buf1, e, p0, po); po += STRIDE;
        }
    } else {
        const int TOT = WARMUP + CHUNK;   // 448 = 28 * 16
        const float4* __restrict__ px =
            x + seq_base + ((size_t)chunk * CHUNK - WARMUP) * ROWF4;
        load_batch(buf0, px); px += STRIDE;
#pragma unroll 1
        for (int t0 = 0; t0 < TOT; t0 += 2 * UB) {
            load_batch(buf1, px); px += STRIDE;
            bool stA = (t0 >= WARMUP);
            proc_const(buf0, e, po, stA);
            if (stA) po += STRIDE;
            if (t0 + 2 * UB < TOT) { load_batch(buf0, px); px += STRIDE; }
            bool stB = (t0 + UB >= WARMUP);
            proc_const(buf1, e, po, stB);
            if (stB) po += STRIDE;
        }
    }
}

extern "C" void kernel_launch(void* const* d_in, const int* in_sizes, int n_in,
                              void* d_out, int out_size) {
    const float* x = (const float*)d_in[0];
    float* out = (float*)d_out;
    // 32 b * 16 chunks * 2 f-groups * 32 lanes = 32768 threads = 1024 warps
    int total = B_DIM * NCHUNK * 2 * 32;
    ema_f4_kernel<<<total / 128, 128>>>(x, out);
}

// round 5
// speedup vs baseline: 1.1624x; 1.1624x over previous
#include <cuda_runtime.h>

// EMA over x[32, 4096, 256] fp32, adjust=True, period=25.
// Round-5: scalar lanes (round-3 structure, proven DRAM-traffic-optimal) with
// load-balance fixes:
//   - 32-thread blocks, 2048 blocks -> 13.84 avg / 14 max blocks per SM
//     (wave-quantization loss 15.6% -> 1.2%)
//   - equal steps per warp: chunk0 has no warmup so it gets a longer chunk.
//     L=480 for chunks 1..7, L0=736 for chunk 0, warmup W=256:
//     every warp runs exactly 736 steps = 92 batches of 8 (even -> clean
//     double-buffered pipeline).
// Chunk 0 uses the exact adjusted recurrence for its first 256 steps
// (reciprocals off the critical FFMA chain), then switches to constant
// coefficients (w_t == 1.0f exactly in fp32 for t >= 207).

#define B_DIM   32
#define T_DIM   4096
#define F_DIM   256
#define NCHUNK  8
#define L_MAIN  480
#define L_ZERO  736          // 7*480 + 736 = 4096
#define WARMUP  256
#define UB      8
#define NBATCH  92           // 736 / 8, even

#define ALPHA_C (2.0f / 26.0f)
#define OMA_C   (1.0f - ALPHA_C)

__device__ __forceinline__ void load_batch(float (&d)[UB],
                                           const float* __restrict__ p) {
#pragma unroll
    for (int i = 0; i < UB; i++)
        d[i] = __ldg(p + (size_t)i * F_DIM);
}

// Constant-coefficient batch (w_t == 1): optional store.
__device__ __forceinline__ void proc_const(const float (&xv)[UB], float& e,
                                           float* __restrict__ po, bool st) {
#pragma unroll
    for (int i = 0; i < UB; i++) {
        e = fmaf(OMA_C, e, ALPHA_C * xv[i]);
        if (st) po[(size_t)i * F_DIM] = e;
    }
}

// Exact adjusted recurrence batch; p0 = oma^{t0} on entry. Always stores.
__device__ __forceinline__ void proc_adj(const float (&xv)[UB], float& e,
                                         float& p0, float* __restrict__ po) {
    float rw[UB];
    float q = 1.0f;
#pragma unroll
    for (int i = 0; i < UB; i++) {
        q *= OMA_C;                    // compile-time powers
        float wt = 1.0f - p0 * q;      // >= alpha, never degenerate
        rw[i] = __fdividef(1.0f, wt);
    }
    p0 *= q;
#pragma unroll
    for (int i = 0; i < UB; i++) {
        e = fmaf(OMA_C * rw[i], e, (ALPHA_C * rw[i]) * xv[i]);
        po[(size_t)i * F_DIM] = e;
    }
}

__global__ void __launch_bounds__(32)
ema_balanced_kernel(const float* __restrict__ x, float* __restrict__ out) {
    int lane  = threadIdx.x;
    int w     = blockIdx.x;             // warp id 0..2047
    int f_hi  = w & 7;                  // 8 groups of 32 features
    int chunk = (w >> 3) & (NCHUNK - 1);
    int b     = w >> 6;
    int f     = f_hi * 32 + lane;

    size_t seq_base = ((size_t)b * T_DIM) * F_DIM + f;
    const size_t STRIDE = (size_t)UB * F_DIM;

    // Read range start and store range start (in timesteps)
    int t_store = (chunk == 0) ? 0 : L_ZERO + (chunk - 1) * L_MAIN;
    int t_read  = (chunk == 0) ? 0 : t_store - WARMUP;
    // Batches: [0, nAdj) adjusted+store (chunk0 only),
    //          [0, warmB) warmup no-store (chunks>=1),
    //          rest constant+store.
    int nAdj  = (chunk == 0) ? (WARMUP / UB) : 0;   // 32
    int warmB = (chunk == 0) ? 0 : (WARMUP / UB);   // 32

    const float* __restrict__ px = x   + seq_base + (size_t)t_read  * F_DIM;
    float*       __restrict__ po = out + seq_base + (size_t)t_store * F_DIM;

    float e  = 0.0f;
    float p0 = 1.0f;
    float buf0[UB], buf1[UB];

    load_batch(buf0, px); px += STRIDE;
#pragma unroll 1
    for (int bt = 0; bt < NBATCH; bt += 2) {
        load_batch(buf1, px); px += STRIDE;
        if (bt < nAdj) {
            proc_adj(buf0, e, p0, po); po += STRIDE;
        } else {
            bool st = (bt >= warmB);
            proc_const(buf0, e, po, st);
            if (st) po += STRIDE;
        }
        if (bt + 2 < NBATCH) { load_batch(buf0, px); px += STRIDE; }
        if (bt + 1 < nAdj) {
            proc_adj(buf1, e, p0, po); po += STRIDE;
        } else {
            bool st = (bt + 1 >= warmB);
            proc_const(buf1, e, po, st);
            if (st) po += STRIDE;
        }
    }
}

extern "C" void kernel_launch(void* const* d_in, const int* in_sizes, int n_in,
                              void* d_out, int out_size) {
    const float* x = (const float*)d_in[0];
    float* out = (float*)d_out;
    // 32 b * 8 chunks * 8 f-groups = 2048 warps, one warp per block
    ema_balanced_kernel<<<B_DIM * NCHUNK * 8, 32>>>(x, out);
}

// round 6
// speedup vs baseline: 1.4258x; 1.2267x over previous
#include <cuda_runtime.h>

// EMA over x[32, 4096, 256] fp32, adjust=True, period=25.
// Round-6: round-3 structure (proven best: scalar lanes, 8 chunks of 512,
// warmup 192 from e=0, 2048 warps) with pipeline depth raised from 2 to 3:
// four rotating UB=16 buffers keep 48 LDGs in flight per warp (M_max ~55).
// Evidence: DRAM% tracks outstanding-loads-per-warp (16 -> 60%, 32 -> 69%).
// Also 64-thread blocks (1024 blocks, 6.92/SM) to trim wave quantization.

#define B_DIM   32
#define T_DIM   4096
#define F_DIM   256
#define CHUNK   512
#define NCHUNK  8
#define WARMUP  192
#define UB      16
#define NB_MAIN ((WARMUP + CHUNK) / UB)   // 44
#define NB_ZERO (CHUNK / UB)              // 32
#define WARM_B  (WARMUP / UB)             // 12

#define ALPHA_C (2.0f / 26.0f)
#define OMA_C   (1.0f - ALPHA_C)

__device__ __forceinline__ void load_batch(float (&d)[UB],
                                           const float* __restrict__ p) {
#pragma unroll
    for (int i = 0; i < UB; i++)
        d[i] = __ldg(p + (size_t)i * F_DIM);
}

// Constant-coefficient batch (w_t == 1.0f exactly for t >= 207).
__device__ __forceinline__ void proc_const(const float (&xv)[UB], float& e,
                                           float* __restrict__ po, bool st) {
#pragma unroll
    for (int i = 0; i < UB; i++) {
        e = fmaf(OMA_C, e, ALPHA_C * xv[i]);
        if (st) po[(size_t)i * F_DIM] = e;
    }
}

// Exact adjusted recurrence; p0 = oma^{t0} on entry. Reciprocals off-chain.
__device__ __forceinline__ void proc_adj(const float (&xv)[UB], float& e,
                                         float& p0, float* __restrict__ po) {
    float rw[UB];
    float q = 1.0f;
#pragma unroll
    for (int i = 0; i < UB; i++) {
        q *= OMA_C;                    // compile-time powers
        float wt = 1.0f - p0 * q;      // >= alpha, never degenerate
        rw[i] = __fdividef(1.0f, wt);
    }
    p0 *= q;
#pragma unroll
    for (int i = 0; i < UB; i++) {
        e = fmaf(OMA_C * rw[i], e, (ALPHA_C * rw[i]) * xv[i]);
        po[(size_t)i * F_DIM] = e;
    }
}

__global__ void __launch_bounds__(64)
ema_mlp_kernel(const float* __restrict__ x, float* __restrict__ out) {
    int g     = blockIdx.x * 64 + threadIdx.x;
    int lane  = g & 31;
    int w     = g >> 5;                 // warp id 0..2047
    int f_hi  = w & 7;
    int chunk = (w >> 3) & (NCHUNK - 1);
    int b     = w >> 6;
    int f     = f_hi * 32 + lane;

    size_t seq_base = ((size_t)b * T_DIM) * F_DIM + f;
    const size_t STRIDE = (size_t)UB * F_DIM;
    float* __restrict__ po = out + seq_base + (size_t)chunk * CHUNK * F_DIM;

    float e = 0.0f;
    float bA[UB], bB[UB], bC[UB], bD[UB];

    if (chunk == 0) {
        // 512 exact-adjusted steps from t=0 (e_{-1}=0 gives e_0 = x_0).
        const float* __restrict__ px = x + seq_base;
        float p0 = 1.0f;
        load_batch(bA, px); px += STRIDE;
        load_batch(bB, px); px += STRIDE;
        load_batch(bC, px); px += STRIDE;
#pragma unroll 1
        for (int bt = 0; bt < NB_ZERO; bt += 4) {
            if (bt + 3 < NB_ZERO) { load_batch(bD, px); px += STRIDE; }
            proc_adj(bA, e, p0, po); po += STRIDE;
            if (bt + 4 < NB_ZERO) { load_batch(bA, px); px += STRIDE; }
            proc_adj(bB, e, p0, po); po += STRIDE;
            if (bt + 5 < NB_ZERO) { load_batch(bB, px); px += STRIDE; }
            proc_adj(bC, e, p0, po); po += STRIDE;
            if (bt + 6 < NB_ZERO) { load_batch(bC, px); px += STRIDE; }
            proc_adj(bD, e, p0, po); po += STRIDE;
        }
    } else {
        // 192 warmup steps (no store) + 512 constant-coefficient steps.
        const float* __restrict__ px =
            x + seq_base + ((size_t)chunk * CHUNK - WARMUP) * F_DIM;
        load_batch(bA, px); px += STRIDE;
        load_batch(bB, px); px += STRIDE;
        load_batch(bC, px); px += STRIDE;
#pragma unroll 1
        for (int bt = 0; bt < NB_MAIN; bt += 4) {
            bool s0 = (bt     >= WARM_B);
            bool s1 = (bt + 1 >= WARM_B);
            bool s2 = (bt + 2 >= WARM_B);
            bool s3 = (bt + 3 >= WARM_B);
            if (bt + 3 < NB_MAIN) { load_batch(bD, px); px += STRIDE; }
            proc_const(bA, e, po, s0); if (s0) po += STRIDE;
            if (bt + 4 < NB_MAIN) { load_batch(bA, px); px += STRIDE; }
            proc_const(bB, e, po, s1); if (s1) po += STRIDE;
            if (bt + 5 < NB_MAIN) { load_batch(bB, px); px += STRIDE; }
            proc_const(bC, e, po, s2); if (s2) po += STRIDE;
            if (bt + 6 < NB_MAIN) { load_batch(bC, px); px += STRIDE; }
            proc_const(bD, e, po, s3); if (s3) po += STRIDE;
        }
    }
}

extern "C" void kernel_launch(void* const* d_in, const int* in_sizes, int n_in,
                              void* d_out, int out_size) {
    const float* x = (const float*)d_in[0];
    float* out = (float*)d_out;
    // 2048 warps, 2 per block -> 1024 blocks (6.92 avg / 7 max per SM)
    ema_mlp_kernel<<<1024, 64>>>(x, out);
}